// round 13
// baseline (speedup 1.0000x reference)
#include <cuda_runtime.h>
#include <cuda_fp16.h>
#include <cstdint>

// ---------------------------------------------------------------------------
// CrossOnlyAttention  (B=64, T=469, C=1024, H=16, hd=64)
// Round 12 (resubmit after infra failure): GEMM restructured to 256x128 CTA
// tile, 8 warps (4x2), 64x64 warp tiles (32 MMAs per 8 LDSM, was 16 per 6).
// BK=64, 3-stage ring, 8-way swizzle. 1 CTA/SM. Attention unchanged.
// ---------------------------------------------------------------------------

#define TSEQ   469
#define NB     64
#define NC     1024
#define NH     16
#define HD     64
#define MROWS  (NB * TSEQ)   // 30016
#define NQKV   (3 * NC)      // 3072
#define GK     1024

typedef __half f16;

__device__ f16 g_a_h[(size_t)MROWS * NC];        // activations (x, then y)
__device__ f16 g_qkv_h[(size_t)MROWS * NQKV];    // qkv
__device__ f16 g_wq_h[(size_t)NQKV * GK];        // W_attn^T
__device__ f16 g_wp_h[(size_t)NC * GK];          // W_proj^T

// ---------------------------------------------------------------------------
// helpers
// ---------------------------------------------------------------------------
__device__ __forceinline__ uint32_t smem_u32(const void* p) {
    uint32_t a;
    asm("{ .reg .u64 t; cvta.to.shared.u64 t, %1; cvt.u32.u64 %0, t; }" : "=r"(a) : "l"(p));
    return a;
}

#define CP_ASYNC16(dst, src, sz) \
    asm volatile("cp.async.cg.shared.global [%0], [%1], 16, %2;" \
                 :: "r"(dst), "l"(src), "r"(sz) : "memory")
#define CP_COMMIT() asm volatile("cp.async.commit_group;" ::: "memory")
#define CP_WAIT(N)  asm volatile("cp.async.wait_group %0;" :: "n"(N) : "memory")

__device__ __forceinline__ void ldmatrix_x4(uint32_t* r, uint32_t addr) {
    asm volatile("ldmatrix.sync.aligned.m8n8.x4.shared.b16 {%0,%1,%2,%3}, [%4];"
                 : "=r"(r[0]), "=r"(r[1]), "=r"(r[2]), "=r"(r[3]) : "r"(addr));
}
__device__ __forceinline__ void ldmatrix_x4_trans(uint32_t* r, uint32_t addr) {
    asm volatile("ldmatrix.sync.aligned.m8n8.x4.trans.shared.b16 {%0,%1,%2,%3}, [%4];"
                 : "=r"(r[0]), "=r"(r[1]), "=r"(r[2]), "=r"(r[3]) : "r"(addr));
}
__device__ __forceinline__ void mma_f16(float* c, const uint32_t* a, const uint32_t* b) {
    asm volatile("mma.sync.aligned.m16n8k16.row.col.f32.f16.f16.f32 "
                 "{%0,%1,%2,%3},{%4,%5,%6,%7},{%8,%9},{%0,%1,%2,%3};"
                 : "+f"(c[0]), "+f"(c[1]), "+f"(c[2]), "+f"(c[3])
                 : "r"(a[0]), "r"(a[1]), "r"(a[2]), "r"(a[3]), "r"(b[0]), "r"(b[1]));
}
__device__ __forceinline__ uint32_t pack_f16(float a, float b) {
    __half2 h = __floats2half2_rn(a, b);
    return *(uint32_t*)&h;
}

// ---------------------------------------------------------------------------
// conversion kernels
// ---------------------------------------------------------------------------
__global__ void cvt_f16(const float* __restrict__ src, f16* __restrict__ dst, size_t n4)
{
    size_t i = (size_t)blockIdx.x * blockDim.x + threadIdx.x;
    if (i >= n4) return;
    float4 v = ((const float4*)src)[i];
    __half2 a = __floats2half2_rn(v.x, v.y);
    __half2 b = __floats2half2_rn(v.z, v.w);
    uint2 o; o.x = *(uint32_t*)&a; o.y = *(uint32_t*)&b;
    ((uint2*)dst)[i] = o;
}

// src [K][N] fp32 -> dst [N][K] f16
__global__ void transpose_f16(const float* __restrict__ src,
                              f16* __restrict__ dst, int K, int N)
{
    __shared__ float tile[32][33];
    const int n0 = blockIdx.x * 32, k0 = blockIdx.y * 32;
    const int tx = threadIdx.x & 31, ty0 = threadIdx.x >> 5;
#pragma unroll
    for (int i = 0; i < 4; i++) {
        int ty = ty0 + i * 8;
        tile[ty][tx] = src[(size_t)(k0 + ty) * N + n0 + tx];
    }
    __syncthreads();
#pragma unroll
    for (int i = 0; i < 4; i++) {
        int ty = ty0 + i * 8;
        dst[(size_t)(n0 + ty) * K + k0 + tx] = __float2half_rn(tile[tx][ty]);
    }
}

// ---------------------------------------------------------------------------
// fp16 GEMM: out[M,N] = A[M,GK] @ B[N,GK]^T + bias
// 256x128 CTA tile, 8 warps (4x2), 64x64 warp tiles, BK=64, 3-stage ring,
// 128B rows w/ 8-way swizzle, 1 CTA/SM.
// ---------------------------------------------------------------------------
#define BK        64
#define NCHUNK    (GK / BK)              // 16
#define TILE_A    32768                  // 256 rows x 128 B
#define TILE_B    16384                  // 128 rows x 128 B
#define STAGE_BYTES (TILE_A + TILE_B)    // 49152
#define GEMM_SMEM  (3 * STAGE_BYTES)     // 147456

// store element (r, seg) -> r*128 + ((seg ^ (r&7))*16)
template <int ROWS>
__device__ __forceinline__ void tile_cp(const f16* __restrict__ src,
                                        int row0, int maxrow, int k0,
                                        uint32_t sdst, int tid)
{
#pragma unroll
    for (int i = 0; i < ROWS / 32; i++) {          // ROWS*8/256 iters
        const int idx = tid + i * 256;
        const int r = idx >> 3, seg = idx & 7;
        const int gr = row0 + r;
        const int ok = (gr < maxrow) ? 16 : 0;
        const f16* gp = src + (size_t)min(gr, maxrow - 1) * GK + k0 + seg * 8;
        CP_ASYNC16(sdst + r * 128 + ((seg ^ (r & 7)) << 4), gp, ok);
    }
}

__global__ void __launch_bounds__(256, 1)
gemm_f16(const f16* __restrict__ A, const f16* __restrict__ B,
         const float* __restrict__ bias,
         float* __restrict__ outF, f16* __restrict__ outH,
         int M, int N)
{
    extern __shared__ char smem[];
    const uint32_t sbase = smem_u32(smem);
    const int tid = threadIdx.x, wid = tid >> 5, lane = tid & 31;
    const int warpM = wid >> 1, warpN = wid & 1;       // 4x2
    const int n0 = blockIdx.x * 128, m0 = blockIdx.y * 256;

    float acc[4][8][4];
#pragma unroll
    for (int i = 0; i < 4; i++)
#pragma unroll
        for (int j = 0; j < 8; j++)
#pragma unroll
            for (int q = 0; q < 4; q++) acc[i][j][q] = 0.f;

    // 8-way swizzle: row term == (lane&7) (all mi/np/warp row offsets %8==0)
    const uint32_t swz = lane & 7;
    const uint32_t aBase = (uint32_t)(warpM * 64 + (lane & 15)) * 128;
    const uint32_t bBase = (uint32_t)(warpN * 64 + (lane & 7) + ((lane >> 4) << 3)) * 128;
    uint32_t aChunk[4], bChunk[4];
#pragma unroll
    for (int ks = 0; ks < 4; ks++) {
        aChunk[ks] = (((uint32_t)(ks * 2) + (lane >> 4)) ^ swz) << 4;
        bChunk[ks] = (((uint32_t)(ks * 2) + ((lane >> 3) & 1)) ^ swz) << 4;
    }

    // prologue: stages 0, 1
    tile_cp<256>(A, m0, M, 0, sbase, tid);
    tile_cp<128>(B, n0, N, 0, sbase + TILE_A, tid);
    CP_COMMIT();
    tile_cp<256>(A, m0, M, BK, sbase + STAGE_BYTES, tid);
    tile_cp<128>(B, n0, N, BK, sbase + STAGE_BYTES + TILE_A, tid);
    CP_COMMIT();

    for (int c = 0; c < NCHUNK; c++) {
        if (c + 1 < NCHUNK) { CP_WAIT(1); } else { CP_WAIT(0); }
        __syncthreads();

        if (c + 2 < NCHUNK) {
            const uint32_t st = sbase + ((c + 2) % 3) * STAGE_BYTES;
            const int k0 = (c + 2) * BK;
            tile_cp<256>(A, m0, M, k0, st, tid);
            tile_cp<128>(B, n0, N, k0, st + TILE_A, tid);
            CP_COMMIT();
        }

        const uint32_t st = sbase + (c % 3) * STAGE_BYTES;
        const uint32_t sA = st, sB = st + TILE_A;

#pragma unroll
        for (int ks = 0; ks < 4; ks++) {
            uint32_t b4[4][4];
#pragma unroll
            for (int np = 0; np < 4; np++) {
                const uint32_t bo = bBase + (uint32_t)(np * 16) * 128 + bChunk[ks];
                ldmatrix_x4(b4[np], sB + bo);
            }
#pragma unroll
            for (int mi = 0; mi < 4; mi++) {
                const uint32_t ao = aBase + (uint32_t)(mi * 16) * 128 + aChunk[ks];
                uint32_t av[4];
                ldmatrix_x4(av, sA + ao);
#pragma unroll
                for (int ni = 0; ni < 8; ni++)
                    mma_f16(acc[mi][ni], av, &b4[ni >> 1][(ni & 1) * 2]);
            }
        }
    }

    const int cBase = n0 + warpN * 64 + (lane & 3) * 2;
    const int rBase = m0 + warpM * 64 + (lane >> 2);
#pragma unroll
    for (int mi = 0; mi < 4; mi++) {
#pragma unroll
        for (int ni = 0; ni < 8; ni++) {
            const int col = cBase + ni * 8;
            const float b0 = bias[col], b1 = bias[col + 1];
#pragma unroll
            for (int half = 0; half < 2; half++) {
                const int r = rBase + mi * 16 + half * 8;
                if (r >= M) continue;
                const float v0 = acc[mi][ni][half * 2 + 0] + b0;
                const float v1 = acc[mi][ni][half * 2 + 1] + b1;
                const size_t o = (size_t)r * N + col;
                if (outH) {
                    __half2 hh = __floats2half2_rn(v0, v1);
                    *(__half2*)(outH + o) = hh;
                } else {
                    *(float2*)(outF + o) = make_float2(v0, v1);
                }
            }
        }
    }
}

// ---------------------------------------------------------------------------
// flash attention (unchanged): fp16, 128 q-rows/CTA, online softmax,
// 3-stage K/V ring, 2 CTAs/SM.
// ---------------------------------------------------------------------------
#define AQR    128
#define NKB    8
#define APB    144

#define OFF_QH   0
#define OFF_KV   (128 * APB)                 // 18432
#define KVSTG    (2 * 64 * APB)              // 18432: K, V
#define ATTN_SMEM (OFF_KV + 3 * KVSTG)       // 73728

__device__ __forceinline__ float cross_bias(int i, int j)
{
    if (i == 0 || j == 0) return 1.0f;
    return ((i <= 234) != (j <= 234)) ? 1.0f : 0.0f;
}

__device__ __forceinline__ void kv_stage(const f16* khg, const f16* vhg,
                                         int j0, uint32_t buf, int tid)
{
#pragma unroll
    for (int i = 0; i < 2; i++) {
        const int idx = tid + i * 256;
        const int r = idx >> 3, seg = idx & 7;
        const int ok = (j0 + r < TSEQ) ? 16 : 0;
        const size_t g = (size_t)(j0 + r) * NQKV + seg * 8;
        const uint32_t s = buf + r * APB + seg * 16;
        CP_ASYNC16(s,            khg + g, ok);
        CP_ASYNC16(s + 64 * APB, vhg + g, ok);
    }
}

__global__ void __launch_bounds__(256, 2)
attn_flash()
{
    extern __shared__ char smem[];
    const uint32_t sbase = smem_u32(smem);

    const int tid = threadIdx.x, wid = tid >> 5, lane = tid & 31;
    const int bh = blockIdx.y;
    const int b  = bh >> 4, h = bh & 15;
    const int q0 = blockIdx.x * AQR;

    const size_t rowb = (size_t)b * TSEQ * NQKV + h * HD;
    const f16* qhg = g_qkv_h + rowb;
    const f16* khg = qhg + NC;
    const f16* vhg = qhg + 2 * NC;

#pragma unroll
    for (int i = 0; i < 4; i++) {
        const int idx = tid + i * 256;
        const int r = idx >> 3, seg = idx & 7;
        const int ok = (q0 + r < TSEQ) ? 16 : 0;
        CP_ASYNC16(sbase + OFF_QH + r * APB + seg * 16,
                   qhg + (size_t)(q0 + r) * NQKV + seg * 8, ok);
    }
    kv_stage(khg, vhg, 0, sbase + OFF_KV, tid);
    CP_COMMIT();
    kv_stage(khg, vhg, 64, sbase + OFF_KV + KVSTG, tid);
    CP_COMMIT();

    const uint32_t aRowQ = (uint32_t)(wid * 16 + (lane & 15)) * APB;
    const uint32_t aColQ = (uint32_t)((lane >> 4) * 8) * 2;
    const uint32_t kRow4 = (uint32_t)((lane & 7) + ((lane >> 4) << 3)) * APB;
    const uint32_t kColB = (uint32_t)(((lane >> 3) & 1) * 8) * 2;
    const uint32_t vRow4 = (uint32_t)((lane & 7) + ((lane >> 3) & 1) * 8) * APB;
    const uint32_t vCol4 = (uint32_t)((lane >> 4) << 3) * 2;

    uint32_t qf[4][4];
    float yc[8][4];
    float m_run[2] = {-1e30f, -1e30f};
    float s_run[2] = {0.f, 0.f};
#pragma unroll
    for (int ni = 0; ni < 8; ni++)
#pragma unroll
        for (int q = 0; q < 4; q++) yc[ni][q] = 0.f;

    for (int c = 0; c < NKB; c++) {
        if (c + 1 < NKB) { CP_WAIT(1); } else { CP_WAIT(0); }
        __syncthreads();

        if (c + 2 < NKB) {
            kv_stage(khg, vhg, (c + 2) * 64,
                     sbase + OFF_KV + ((c + 2) % 3) * KVSTG, tid);
            CP_COMMIT();
        }

        if (c == 0) {
#pragma unroll
            for (int ks = 0; ks < 4; ks++)
                ldmatrix_x4(qf[ks], sbase + OFF_QH + aRowQ + aColQ + ks * 32);
        }

        const uint32_t stg = sbase + OFF_KV + (c % 3) * KVSTG;
        const uint32_t skh = stg, svh = stg + 64 * APB;

        float sc[8][4];
#pragma unroll
        for (int ni = 0; ni < 8; ni++)
#pragma unroll
            for (int q = 0; q < 4; q++) sc[ni][q] = 0.f;

#pragma unroll
        for (int ks = 0; ks < 4; ks++) {
#pragma unroll
            for (int np = 0; np < 4; np++) {
                uint32_t k4[4];
                const uint32_t bo = kRow4 + (uint32_t)(np * 16) * APB + kColB + ks * 32;
                ldmatrix_x4(k4, skh + bo);
                mma_f16(sc[np * 2 + 0], qf[ks], &k4[0]);
                mma_f16(sc[np * 2 + 1], qf[ks], &k4[2]);
            }
        }

        const int j0 = c * 64;
#pragma unroll
        for (int ni = 0; ni < 8; ni++) {
#pragma unroll
            for (int q = 0; q < 4; q++) {
                const int e = q & 1, hh = q >> 1;
                const int jg = j0 + ni * 8 + (lane & 3) * 2 + e;
                const int qi = q0 + wid * 16 + (lane >> 2) + hh * 8;
                const float v = sc[ni][q] * 0.125f + cross_bias(qi, jg);
                sc[ni][q] = (jg < TSEQ) ? v : -1e30f;
            }
        }

#pragma unroll
        for (int hh = 0; hh < 2; hh++) {
            float mb = -1e30f;
#pragma unroll
            for (int ni = 0; ni < 8; ni++)
                mb = fmaxf(mb, fmaxf(sc[ni][hh * 2], sc[ni][hh * 2 + 1]));
            mb = fmaxf(mb, __shfl_xor_sync(0xffffffffu, mb, 1));
            mb = fmaxf(mb, __shfl_xor_sync(0xffffffffu, mb, 2));
            const float mn = fmaxf(m_run[hh], mb);
            const float f = __expf(m_run[hh] - mn);
            m_run[hh] = mn;
            float sb = 0.f;
#pragma unroll
            for (int ni = 0; ni < 8; ni++) {
                const float p0 = __expf(sc[ni][hh * 2] - mn);
                const float p1 = __expf(sc[ni][hh * 2 + 1] - mn);
                sc[ni][hh * 2] = p0; sc[ni][hh * 2 + 1] = p1;
                sb += p0 + p1;
            }
            sb += __shfl_xor_sync(0xffffffffu, sb, 1);
            sb += __shfl_xor_sync(0xffffffffu, sb, 2);
            s_run[hh] = s_run[hh] * f + sb;
#pragma unroll
            for (int ni = 0; ni < 8; ni++) {
                yc[ni][hh * 2]     *= f;
                yc[ni][hh * 2 + 1] *= f;
            }
        }

#pragma unroll
        for (int kk = 0; kk < 4; kk++) {
            uint32_t pa[4];
#pragma unroll
            for (int t = 0; t < 2; t++) {
                const float* s0 = sc[kk * 2 + t];
                pa[t * 2 + 0] = pack_f16(s0[0], s0[1]);
                pa[t * 2 + 1] = pack_f16(s0[2], s0[3]);
            }
#pragma unroll
            for (int np = 0; np < 4; np++) {
                uint32_t v4[4];
                const uint32_t vo = vRow4 + (uint32_t)(kk * 16) * APB
                                  + (uint32_t)(np * 16) * 2 + vCol4;
                ldmatrix_x4_trans(v4, svh + vo);
                mma_f16(yc[np * 2 + 0], pa, &v4[0]);
                mma_f16(yc[np * 2 + 1], pa, &v4[2]);
            }
        }
    }

#pragma unroll
    for (int hh = 0; hh < 2; hh++) {
        const float ri = 1.0f / s_run[hh];
        const int r = wid * 16 + (lane >> 2) + hh * 8;
        const int t = q0 + r;
        if (t >= TSEQ) continue;
        const size_t base = ((size_t)b * TSEQ + t) * NC + h * HD;
#pragma unroll
        for (int ni = 0; ni < 8; ni++) {
            const int d = ni * 8 + (lane & 3) * 2;
            __half2 hv = __floats2half2_rn(yc[ni][hh * 2] * ri, yc[ni][hh * 2 + 1] * ri);
            *(__half2*)(g_a_h + base + d) = hv;
        }
    }
}

// ---------------------------------------------------------------------------
extern "C" void kernel_launch(void* const* d_in, const int* in_sizes, int n_in,
                              void* d_out, int out_size)
{
    const float* x      = (const float*)d_in[0];
    const float* W_attn = (const float*)d_in[1];
    const float* b_attn = (const float*)d_in[2];
    const float* W_proj = (const float*)d_in[3];
    const float* b_proj = (const float*)d_in[4];
    float* out = (float*)d_out;

    cudaFuncSetAttribute(gemm_f16, cudaFuncAttributeMaxDynamicSharedMemorySize, GEMM_SMEM);
    cudaFuncSetAttribute(attn_flash, cudaFuncAttributeMaxDynamicSharedMemorySize, ATTN_SMEM);

    void *pAh, *pQh, *pWqH, *pWpH;
    cudaGetSymbolAddress(&pAh,  g_a_h);
    cudaGetSymbolAddress(&pQh,  g_qkv_h);
    cudaGetSymbolAddress(&pWqH, g_wq_h);
    cudaGetSymbolAddress(&pWpH, g_wp_h);

    const size_t n4 = (size_t)MROWS * NC / 4;
    cvt_f16<<<(int)((n4 + 255) / 256), 256>>>(x, (f16*)pAh, n4);
    transpose_f16<<<dim3(NQKV / 32, GK / 32), 256>>>(W_attn, (f16*)pWqH, GK, NQKV);
    transpose_f16<<<dim3(NC / 32, GK / 32), 256>>>(W_proj, (f16*)pWpH, GK, NC);

    // qkv = x @ W_attn + b_attn
    dim3 g1(NQKV / 128, (MROWS + 255) / 256);
    gemm_f16<<<g1, 256, GEMM_SMEM>>>((f16*)pAh, (f16*)pWqH, b_attn,
                                     nullptr, (f16*)pQh, MROWS, NQKV);

    // attention (writes y into g_a_h)
    dim3 ga((TSEQ + AQR - 1) / AQR, NB * NH);
    attn_flash<<<ga, 256, ATTN_SMEM>>>();

    // out = y @ W_proj + b_proj
    dim3 g2(NC / 128, (MROWS + 255) / 256);
    gemm_f16<<<g2, 256, GEMM_SMEM>>>((f16*)pAh, (f16*)pWpH, b_proj,
                                     out, nullptr, MROWS, NC);
}

// round 14
// speedup vs baseline: 1.1396x; 1.1396x over previous
#include <cuda_runtime.h>
#include <cuda_fp16.h>
#include <cstdint>

// ---------------------------------------------------------------------------
// CrossOnlyAttention  (B=64, T=469, C=1024, H=16, hd=64)
// Round 14: GEMM = 128x128 CTA tile, 128 threads (2x2 warps), 64x64 warp
// tiles, BK=64, 3-stage ring, 8-way swizzle, 2 CTAs/SM — combines R10's
// cross-CTA barrier overlap with R12's 4.0 MMA/LDSM ratio.
// Attention unchanged.
// ---------------------------------------------------------------------------

#define TSEQ   469
#define NB     64
#define NC     1024
#define NH     16
#define HD     64
#define MROWS  (NB * TSEQ)   // 30016
#define NQKV   (3 * NC)      // 3072
#define GK     1024

typedef __half f16;

__device__ f16 g_a_h[(size_t)MROWS * NC];        // activations (x, then y)
__device__ f16 g_qkv_h[(size_t)MROWS * NQKV];    // qkv
__device__ f16 g_wq_h[(size_t)NQKV * GK];        // W_attn^T
__device__ f16 g_wp_h[(size_t)NC * GK];          // W_proj^T

// ---------------------------------------------------------------------------
// helpers
// ---------------------------------------------------------------------------
__device__ __forceinline__ uint32_t smem_u32(const void* p) {
    uint32_t a;
    asm("{ .reg .u64 t; cvta.to.shared.u64 t, %1; cvt.u32.u64 %0, t; }" : "=r"(a) : "l"(p));
    return a;
}

#define CP_ASYNC16(dst, src, sz) \
    asm volatile("cp.async.cg.shared.global [%0], [%1], 16, %2;" \
                 :: "r"(dst), "l"(src), "r"(sz) : "memory")
#define CP_COMMIT() asm volatile("cp.async.commit_group;" ::: "memory")
#define CP_WAIT(N)  asm volatile("cp.async.wait_group %0;" :: "n"(N) : "memory")

__device__ __forceinline__ void ldmatrix_x4(uint32_t* r, uint32_t addr) {
    asm volatile("ldmatrix.sync.aligned.m8n8.x4.shared.b16 {%0,%1,%2,%3}, [%4];"
                 : "=r"(r[0]), "=r"(r[1]), "=r"(r[2]), "=r"(r[3]) : "r"(addr));
}
__device__ __forceinline__ void ldmatrix_x4_trans(uint32_t* r, uint32_t addr) {
    asm volatile("ldmatrix.sync.aligned.m8n8.x4.trans.shared.b16 {%0,%1,%2,%3}, [%4];"
                 : "=r"(r[0]), "=r"(r[1]), "=r"(r[2]), "=r"(r[3]) : "r"(addr));
}
__device__ __forceinline__ void mma_f16(float* c, const uint32_t* a, const uint32_t* b) {
    asm volatile("mma.sync.aligned.m16n8k16.row.col.f32.f16.f16.f32 "
                 "{%0,%1,%2,%3},{%4,%5,%6,%7},{%8,%9},{%0,%1,%2,%3};"
                 : "+f"(c[0]), "+f"(c[1]), "+f"(c[2]), "+f"(c[3])
                 : "r"(a[0]), "r"(a[1]), "r"(a[2]), "r"(a[3]), "r"(b[0]), "r"(b[1]));
}
__device__ __forceinline__ uint32_t pack_f16(float a, float b) {
    __half2 h = __floats2half2_rn(a, b);
    return *(uint32_t*)&h;
}

// ---------------------------------------------------------------------------
// conversion kernels
// ---------------------------------------------------------------------------
__global__ void cvt_f16(const float* __restrict__ src, f16* __restrict__ dst, size_t n4)
{
    size_t i = (size_t)blockIdx.x * blockDim.x + threadIdx.x;
    if (i >= n4) return;
    float4 v = ((const float4*)src)[i];
    __half2 a = __floats2half2_rn(v.x, v.y);
    __half2 b = __floats2half2_rn(v.z, v.w);
    uint2 o; o.x = *(uint32_t*)&a; o.y = *(uint32_t*)&b;
    ((uint2*)dst)[i] = o;
}

// src [K][N] fp32 -> dst [N][K] f16
__global__ void transpose_f16(const float* __restrict__ src,
                              f16* __restrict__ dst, int K, int N)
{
    __shared__ float tile[32][33];
    const int n0 = blockIdx.x * 32, k0 = blockIdx.y * 32;
    const int tx = threadIdx.x & 31, ty0 = threadIdx.x >> 5;
#pragma unroll
    for (int i = 0; i < 4; i++) {
        int ty = ty0 + i * 8;
        tile[ty][tx] = src[(size_t)(k0 + ty) * N + n0 + tx];
    }
    __syncthreads();
#pragma unroll
    for (int i = 0; i < 4; i++) {
        int ty = ty0 + i * 8;
        dst[(size_t)(n0 + ty) * K + k0 + tx] = __float2half_rn(tile[tx][ty]);
    }
}

// ---------------------------------------------------------------------------
// fp16 GEMM: out[M,N] = A[M,GK] @ B[N,GK]^T + bias
// 128x128 CTA tile, 128 threads (2x2 warps), 64x64 warp tiles, BK=64,
// 3-stage ring, 128B rows w/ 8-way swizzle, 2 CTAs/SM.
// ---------------------------------------------------------------------------
#define BK        64
#define NCHUNK    (GK / BK)              // 16
#define TILE_BYTES 16384                 // 128 rows x 128 B
#define STAGE_BYTES (2 * TILE_BYTES)     // A, B = 32768
#define GEMM_SMEM  (3 * STAGE_BYTES)     // 98304

// store element (r, seg) -> r*128 + ((seg ^ (r&7))*16); 128 threads, 8 iters
__device__ __forceinline__ void tile_cp(const f16* __restrict__ src,
                                        int row0, int maxrow, int k0,
                                        uint32_t sdst, int tid)
{
#pragma unroll
    for (int i = 0; i < 8; i++) {
        const int idx = tid + i * 128;       // 0..1023
        const int r = idx >> 3, seg = idx & 7;
        const int gr = row0 + r;
        const int ok = (gr < maxrow) ? 16 : 0;
        const f16* gp = src + (size_t)min(gr, maxrow - 1) * GK + k0 + seg * 8;
        CP_ASYNC16(sdst + r * 128 + ((seg ^ (r & 7)) << 4), gp, ok);
    }
}

__global__ void __launch_bounds__(128, 2)
gemm_f16(const f16* __restrict__ A, const f16* __restrict__ B,
         const float* __restrict__ bias,
         float* __restrict__ outF, f16* __restrict__ outH,
         int M, int N)
{
    extern __shared__ char smem[];
    const uint32_t sbase = smem_u32(smem);
    const int tid = threadIdx.x, wid = tid >> 5, lane = tid & 31;
    const int warpM = wid >> 1, warpN = wid & 1;       // 2x2
    const int n0 = blockIdx.x * 128, m0 = blockIdx.y * 128;

    float acc[4][8][4];
#pragma unroll
    for (int i = 0; i < 4; i++)
#pragma unroll
        for (int j = 0; j < 8; j++)
#pragma unroll
            for (int q = 0; q < 4; q++) acc[i][j][q] = 0.f;

    // 8-way swizzle: row term == (lane&7) (all mi/np/warp row offsets %8==0)
    const uint32_t swz = lane & 7;
    const uint32_t aBase = (uint32_t)(warpM * 64 + (lane & 15)) * 128;
    const uint32_t bBase = (uint32_t)(warpN * 64 + (lane & 7) + ((lane >> 4) << 3)) * 128;
    uint32_t aChunk[4], bChunk[4];
#pragma unroll
    for (int ks = 0; ks < 4; ks++) {
        aChunk[ks] = (((uint32_t)(ks * 2) + (lane >> 4)) ^ swz) << 4;
        bChunk[ks] = (((uint32_t)(ks * 2) + ((lane >> 3) & 1)) ^ swz) << 4;
    }

    // prologue: stages 0, 1
    tile_cp(A, m0, M, 0, sbase, tid);
    tile_cp(B, n0, N, 0, sbase + TILE_BYTES, tid);
    CP_COMMIT();
    tile_cp(A, m0, M, BK, sbase + STAGE_BYTES, tid);
    tile_cp(B, n0, N, BK, sbase + STAGE_BYTES + TILE_BYTES, tid);
    CP_COMMIT();

    for (int c = 0; c < NCHUNK; c++) {
        if (c + 1 < NCHUNK) { CP_WAIT(1); } else { CP_WAIT(0); }
        __syncthreads();

        if (c + 2 < NCHUNK) {
            const uint32_t st = sbase + ((c + 2) % 3) * STAGE_BYTES;
            const int k0 = (c + 2) * BK;
            tile_cp(A, m0, M, k0, st, tid);
            tile_cp(B, n0, N, k0, st + TILE_BYTES, tid);
            CP_COMMIT();
        }

        const uint32_t st = sbase + (c % 3) * STAGE_BYTES;
        const uint32_t sA = st, sB = st + TILE_BYTES;

#pragma unroll
        for (int ks = 0; ks < 4; ks++) {
            uint32_t b4[4][4];
#pragma unroll
            for (int np = 0; np < 4; np++) {
                const uint32_t bo = bBase + (uint32_t)(np * 16) * 128 + bChunk[ks];
                ldmatrix_x4(b4[np], sB + bo);
            }
#pragma unroll
            for (int mi = 0; mi < 4; mi++) {
                const uint32_t ao = aBase + (uint32_t)(mi * 16) * 128 + aChunk[ks];
                uint32_t av[4];
                ldmatrix_x4(av, sA + ao);
#pragma unroll
                for (int ni = 0; ni < 8; ni++)
                    mma_f16(acc[mi][ni], av, &b4[ni >> 1][(ni & 1) * 2]);
            }
        }
    }

    const int cBase = n0 + warpN * 64 + (lane & 3) * 2;
    const int rBase = m0 + warpM * 64 + (lane >> 2);
#pragma unroll
    for (int mi = 0; mi < 4; mi++) {
#pragma unroll
        for (int ni = 0; ni < 8; ni++) {
            const int col = cBase + ni * 8;
            const float b0 = bias[col], b1 = bias[col + 1];
#pragma unroll
            for (int half = 0; half < 2; half++) {
                const int r = rBase + mi * 16 + half * 8;
                if (r >= M) continue;
                const float v0 = acc[mi][ni][half * 2 + 0] + b0;
                const float v1 = acc[mi][ni][half * 2 + 1] + b1;
                const size_t o = (size_t)r * N + col;
                if (outH) {
                    __half2 hh = __floats2half2_rn(v0, v1);
                    *(__half2*)(outH + o) = hh;
                } else {
                    *(float2*)(outF + o) = make_float2(v0, v1);
                }
            }
        }
    }
}

// ---------------------------------------------------------------------------
// flash attention (unchanged): fp16, 128 q-rows/CTA, online softmax,
// 3-stage K/V ring, 2 CTAs/SM.
// ---------------------------------------------------------------------------
#define AQR    128
#define NKB    8
#define APB    144

#define OFF_QH   0
#define OFF_KV   (128 * APB)                 // 18432
#define KVSTG    (2 * 64 * APB)              // 18432: K, V
#define ATTN_SMEM (OFF_KV + 3 * KVSTG)       // 73728

__device__ __forceinline__ float cross_bias(int i, int j)
{
    if (i == 0 || j == 0) return 1.0f;
    return ((i <= 234) != (j <= 234)) ? 1.0f : 0.0f;
}

__device__ __forceinline__ void kv_stage(const f16* khg, const f16* vhg,
                                         int j0, uint32_t buf, int tid)
{
#pragma unroll
    for (int i = 0; i < 2; i++) {
        const int idx = tid + i * 256;
        const int r = idx >> 3, seg = idx & 7;
        const int ok = (j0 + r < TSEQ) ? 16 : 0;
        const size_t g = (size_t)(j0 + r) * NQKV + seg * 8;
        const uint32_t s = buf + r * APB + seg * 16;
        CP_ASYNC16(s,            khg + g, ok);
        CP_ASYNC16(s + 64 * APB, vhg + g, ok);
    }
}

__global__ void __launch_bounds__(256, 2)
attn_flash()
{
    extern __shared__ char smem[];
    const uint32_t sbase = smem_u32(smem);

    const int tid = threadIdx.x, wid = tid >> 5, lane = tid & 31;
    const int bh = blockIdx.y;
    const int b  = bh >> 4, h = bh & 15;
    const int q0 = blockIdx.x * AQR;

    const size_t rowb = (size_t)b * TSEQ * NQKV + h * HD;
    const f16* qhg = g_qkv_h + rowb;
    const f16* khg = qhg + NC;
    const f16* vhg = qhg + 2 * NC;

#pragma unroll
    for (int i = 0; i < 4; i++) {
        const int idx = tid + i * 256;
        const int r = idx >> 3, seg = idx & 7;
        const int ok = (q0 + r < TSEQ) ? 16 : 0;
        CP_ASYNC16(sbase + OFF_QH + r * APB + seg * 16,
                   qhg + (size_t)(q0 + r) * NQKV + seg * 8, ok);
    }
    kv_stage(khg, vhg, 0, sbase + OFF_KV, tid);
    CP_COMMIT();
    kv_stage(khg, vhg, 64, sbase + OFF_KV + KVSTG, tid);
    CP_COMMIT();

    const uint32_t aRowQ = (uint32_t)(wid * 16 + (lane & 15)) * APB;
    const uint32_t aColQ = (uint32_t)((lane >> 4) * 8) * 2;
    const uint32_t kRow4 = (uint32_t)((lane & 7) + ((lane >> 4) << 3)) * APB;
    const uint32_t kColB = (uint32_t)(((lane >> 3) & 1) * 8) * 2;
    const uint32_t vRow4 = (uint32_t)((lane & 7) + ((lane >> 3) & 1) * 8) * APB;
    const uint32_t vCol4 = (uint32_t)((lane >> 4) << 3) * 2;

    uint32_t qf[4][4];
    float yc[8][4];
    float m_run[2] = {-1e30f, -1e30f};
    float s_run[2] = {0.f, 0.f};
#pragma unroll
    for (int ni = 0; ni < 8; ni++)
#pragma unroll
        for (int q = 0; q < 4; q++) yc[ni][q] = 0.f;

    for (int c = 0; c < NKB; c++) {
        if (c + 1 < NKB) { CP_WAIT(1); } else { CP_WAIT(0); }
        __syncthreads();

        if (c + 2 < NKB) {
            kv_stage(khg, vhg, (c + 2) * 64,
                     sbase + OFF_KV + ((c + 2) % 3) * KVSTG, tid);
            CP_COMMIT();
        }

        if (c == 0) {
#pragma unroll
            for (int ks = 0; ks < 4; ks++)
                ldmatrix_x4(qf[ks], sbase + OFF_QH + aRowQ + aColQ + ks * 32);
        }

        const uint32_t stg = sbase + OFF_KV + (c % 3) * KVSTG;
        const uint32_t skh = stg, svh = stg + 64 * APB;

        float sc[8][4];
#pragma unroll
        for (int ni = 0; ni < 8; ni++)
#pragma unroll
            for (int q = 0; q < 4; q++) sc[ni][q] = 0.f;

#pragma unroll
        for (int ks = 0; ks < 4; ks++) {
#pragma unroll
            for (int np = 0; np < 4; np++) {
                uint32_t k4[4];
                const uint32_t bo = kRow4 + (uint32_t)(np * 16) * APB + kColB + ks * 32;
                ldmatrix_x4(k4, skh + bo);
                mma_f16(sc[np * 2 + 0], qf[ks], &k4[0]);
                mma_f16(sc[np * 2 + 1], qf[ks], &k4[2]);
            }
        }

        const int j0 = c * 64;
#pragma unroll
        for (int ni = 0; ni < 8; ni++) {
#pragma unroll
            for (int q = 0; q < 4; q++) {
                const int e = q & 1, hh = q >> 1;
                const int jg = j0 + ni * 8 + (lane & 3) * 2 + e;
                const int qi = q0 + wid * 16 + (lane >> 2) + hh * 8;
                const float v = sc[ni][q] * 0.125f + cross_bias(qi, jg);
                sc[ni][q] = (jg < TSEQ) ? v : -1e30f;
            }
        }

#pragma unroll
        for (int hh = 0; hh < 2; hh++) {
            float mb = -1e30f;
#pragma unroll
            for (int ni = 0; ni < 8; ni++)
                mb = fmaxf(mb, fmaxf(sc[ni][hh * 2], sc[ni][hh * 2 + 1]));
            mb = fmaxf(mb, __shfl_xor_sync(0xffffffffu, mb, 1));
            mb = fmaxf(mb, __shfl_xor_sync(0xffffffffu, mb, 2));
            const float mn = fmaxf(m_run[hh], mb);
            const float f = __expf(m_run[hh] - mn);
            m_run[hh] = mn;
            float sb = 0.f;
#pragma unroll
            for (int ni = 0; ni < 8; ni++) {
                const float p0 = __expf(sc[ni][hh * 2] - mn);
                const float p1 = __expf(sc[ni][hh * 2 + 1] - mn);
                sc[ni][hh * 2] = p0; sc[ni][hh * 2 + 1] = p1;
                sb += p0 + p1;
            }
            sb += __shfl_xor_sync(0xffffffffu, sb, 1);
            sb += __shfl_xor_sync(0xffffffffu, sb, 2);
            s_run[hh] = s_run[hh] * f + sb;
#pragma unroll
            for (int ni = 0; ni < 8; ni++) {
                yc[ni][hh * 2]     *= f;
                yc[ni][hh * 2 + 1] *= f;
            }
        }

#pragma unroll
        for (int kk = 0; kk < 4; kk++) {
            uint32_t pa[4];
#pragma unroll
            for (int t = 0; t < 2; t++) {
                const float* s0 = sc[kk * 2 + t];
                pa[t * 2 + 0] = pack_f16(s0[0], s0[1]);
                pa[t * 2 + 1] = pack_f16(s0[2], s0[3]);
            }
#pragma unroll
            for (int np = 0; np < 4; np++) {
                uint32_t v4[4];
                const uint32_t vo = vRow4 + (uint32_t)(kk * 16) * APB
                                  + (uint32_t)(np * 16) * 2 + vCol4;
                ldmatrix_x4_trans(v4, svh + vo);
                mma_f16(yc[np * 2 + 0], pa, &v4[0]);
                mma_f16(yc[np * 2 + 1], pa, &v4[2]);
            }
        }
    }

#pragma unroll
    for (int hh = 0; hh < 2; hh++) {
        const float ri = 1.0f / s_run[hh];
        const int r = wid * 16 + (lane >> 2) + hh * 8;
        const int t = q0 + r;
        if (t >= TSEQ) continue;
        const size_t base = ((size_t)b * TSEQ + t) * NC + h * HD;
#pragma unroll
        for (int ni = 0; ni < 8; ni++) {
            const int d = ni * 8 + (lane & 3) * 2;
            __half2 hv = __floats2half2_rn(yc[ni][hh * 2] * ri, yc[ni][hh * 2 + 1] * ri);
            *(__half2*)(g_a_h + base + d) = hv;
        }
    }
}

// ---------------------------------------------------------------------------
extern "C" void kernel_launch(void* const* d_in, const int* in_sizes, int n_in,
                              void* d_out, int out_size)
{
    const float* x      = (const float*)d_in[0];
    const float* W_attn = (const float*)d_in[1];
    const float* b_attn = (const float*)d_in[2];
    const float* W_proj = (const float*)d_in[3];
    const float* b_proj = (const float*)d_in[4];
    float* out = (float*)d_out;

    cudaFuncSetAttribute(gemm_f16, cudaFuncAttributeMaxDynamicSharedMemorySize, GEMM_SMEM);
    cudaFuncSetAttribute(attn_flash, cudaFuncAttributeMaxDynamicSharedMemorySize, ATTN_SMEM);

    void *pAh, *pQh, *pWqH, *pWpH;
    cudaGetSymbolAddress(&pAh,  g_a_h);
    cudaGetSymbolAddress(&pQh,  g_qkv_h);
    cudaGetSymbolAddress(&pWqH, g_wq_h);
    cudaGetSymbolAddress(&pWpH, g_wp_h);

    const size_t n4 = (size_t)MROWS * NC / 4;
    cvt_f16<<<(int)((n4 + 255) / 256), 256>>>(x, (f16*)pAh, n4);
    transpose_f16<<<dim3(NQKV / 32, GK / 32), 256>>>(W_attn, (f16*)pWqH, GK, NQKV);
    transpose_f16<<<dim3(NC / 32, GK / 32), 256>>>(W_proj, (f16*)pWpH, GK, NC);

    // qkv = x @ W_attn + b_attn
    dim3 g1(NQKV / 128, (MROWS + 127) / 128);
    gemm_f16<<<g1, 128, GEMM_SMEM>>>((f16*)pAh, (f16*)pWqH, b_attn,
                                     nullptr, (f16*)pQh, MROWS, NQKV);

    // attention (writes y into g_a_h)
    dim3 ga((TSEQ + AQR - 1) / AQR, NB * NH);
    attn_flash<<<ga, 256, ATTN_SMEM>>>();

    // out = y @ W_proj + b_proj
    dim3 g2(NC / 128, (MROWS + 127) / 128);
    gemm_f16<<<g2, 128, GEMM_SMEM>>>((f16*)pAh, (f16*)pWpH, b_proj,
                                     out, nullptr, MROWS, NC);
}